// round 1
// baseline (speedup 1.0000x reference)
#include <cuda_runtime.h>
#include <math.h>

#define BATCH   4
#define SEQLEN  4096
#define DMODEL  1024
#define DINNER  2048
#define DSTATE  16
#define NHEADS  8
#define HEADDIM 256
#define CONVDIM 2080            // DINNER + 2*DSTATE
#define DPROJ   4136            // 2*DINNER + 2*DSTATE + NHEADS
#define QC      64
#define NCHUNK  (SEQLEN/QC)     // 64
#define NTOK    (BATCH*SEQLEN)  // 16384

// ---------------- scratch (device globals: allocation-guard-safe) -----------
__device__ float g_zx[(size_t)NTOK * DPROJ];        // in-proj output (z | xBC | dt_raw)
__device__ float g_xbc[(size_t)NTOK * CONVDIM];     // conv+silu output
__device__ float g_dt[NTOK * NHEADS];               // softplus(dt)
__device__ float g_cs[NTOK * NHEADS];               // within-chunk cumsum of dt*A
__device__ float g_states[BATCH * NCHUNK * NHEADS * HEADDIM * DSTATE];
__device__ float g_prev[BATCH * NCHUNK * NHEADS * HEADDIM * DSTATE];
__device__ float g_y[(size_t)NTOK * DINNER];        // Y_diag (+D*x), then += Y_off
__device__ float g_yn[(size_t)NTOK * DINNER];       // gated + normalized

// ---------------- SGEMM: C[M,N] = A[M,K] @ B[K,N], row-major ----------------
// 128x128 block, BK=8, 8x8 microtile, 256 threads. M must be multiple of 128,
// K multiple of 8; N handled with guards (GEMM-in has N=4136).
__global__ void __launch_bounds__(256)
sgemm_kernel(int M, int N, int K,
             const float* __restrict__ A,
             const float* __restrict__ B,
             float* __restrict__ C) {
    const int BM = 128, BN = 128, BK = 8, TM = 8, TN = 8;
    __shared__ float As[BK][BM];
    __shared__ float Bs[BK][BN];

    int tid = threadIdx.x;
    int bx = blockIdx.x, by = blockIdx.y;
    int threadCol = tid & 15;          // 0..15 -> N microtile
    int threadRow = tid >> 4;          // 0..15 -> M microtile
    int innerRowA = tid >> 1;          // 0..127
    int innerColA = (tid & 1) * 4;     // 0 or 4
    int innerRowB = tid >> 5;          // 0..7
    int innerColB = (tid & 31) * 4;    // 0..124

    const float* Ab = A + (size_t)by * BM * K;
    int ncol0 = bx * BN;
    bool nfull = (ncol0 + BN) <= N;

    float acc[TM][TN];
    #pragma unroll
    for (int i = 0; i < TM; i++)
        #pragma unroll
        for (int j = 0; j < TN; j++) acc[i][j] = 0.f;

    for (int k0 = 0; k0 < K; k0 += BK) {
        float4 av = *(const float4*)(Ab + (size_t)innerRowA * K + k0 + innerColA);
        As[innerColA + 0][innerRowA] = av.x;
        As[innerColA + 1][innerRowA] = av.y;
        As[innerColA + 2][innerRowA] = av.z;
        As[innerColA + 3][innerRowA] = av.w;

        if (nfull) {
            float4 bv = *(const float4*)(B + (size_t)(k0 + innerRowB) * N + ncol0 + innerColB);
            *(float4*)&Bs[innerRowB][innerColB] = bv;
        } else {
            #pragma unroll
            for (int j = 0; j < 4; j++) {
                int col = ncol0 + innerColB + j;
                Bs[innerRowB][innerColB + j] =
                    (col < N) ? B[(size_t)(k0 + innerRowB) * N + col] : 0.f;
            }
        }
        __syncthreads();

        #pragma unroll
        for (int k = 0; k < BK; k++) {
            float regM[TM], regN[TN];
            #pragma unroll
            for (int i = 0; i < TM; i++) regM[i] = As[k][threadRow * TM + i];
            #pragma unroll
            for (int j = 0; j < TN; j++) regN[j] = Bs[k][threadCol * TN + j];
            #pragma unroll
            for (int i = 0; i < TM; i++)
                #pragma unroll
                for (int j = 0; j < TN; j++)
                    acc[i][j] += regM[i] * regN[j];
        }
        __syncthreads();
    }

    #pragma unroll
    for (int i = 0; i < TM; i++) {
        size_t row = (size_t)by * BM + threadRow * TM + i;
        #pragma unroll
        for (int j = 0; j < TN; j += 4) {
            int col = ncol0 + threadCol * TN + j;
            if (col + 3 < N) {
                float4 o = make_float4(acc[i][j], acc[i][j + 1], acc[i][j + 2], acc[i][j + 3]);
                *(float4*)(C + row * N + col) = o;
            } else {
                for (int jj = 0; jj < 4; jj++)
                    if (col + jj < N) C[row * N + col + jj] = acc[i][j + jj];
            }
        }
    }
}

// ---------------- dt = softplus(raw + dt_bias) ------------------------------
__global__ void dt_kernel(const float* __restrict__ dt_bias) {
    int i = blockIdx.x * blockDim.x + threadIdx.x; // over NTOK*NHEADS
    int h = i & 7;
    int t = i >> 3;
    float v = g_zx[(size_t)t * DPROJ + DINNER + CONVDIM + h] + dt_bias[h];
    g_dt[i] = (v > 20.f) ? v : log1pf(expf(v));
}

// ---------------- depthwise causal conv (width 4) + silu --------------------
__global__ void conv_silu_kernel(const float* __restrict__ conv_w,
                                 const float* __restrict__ conv_b) {
    int c = blockIdx.x * blockDim.x + threadIdx.x;
    int t = blockIdx.y;
    if (c >= CONVDIM) return;
    int tb = t & (SEQLEN - 1); // position within batch
    float acc = conv_b[c];
    #pragma unroll
    for (int k = 0; k < 4; k++) {
        int off = k - 3;
        if (tb + off >= 0)
            acc += g_zx[(size_t)(t + off) * DPROJ + DINNER + c] * conv_w[c * 4 + k];
    }
    g_xbc[(size_t)t * CONVDIM + c] = acc / (1.f + expf(-acc));
}

// ---------------- per-chunk: cumsum, M=L*S*dt, Y_diag(+D*x), states ---------
__global__ void __launch_bounds__(256)
chunk_kernel(const float* __restrict__ A_log, const float* __restrict__ Dp) {
    int h = blockIdx.x, c = blockIdx.y, b = blockIdx.z;
    int t0 = b * SEQLEN + c * QC;
    int tid = threadIdx.x;

    __shared__ float sB[QC][DSTATE];
    __shared__ float sC[QC][DSTATE];
    __shared__ float sdt[QC], scs[QC];
    __shared__ float sMt[QC][QC];   // transposed: sMt[s][q] = M[q][s]
    __shared__ float sE[QC][DSTATE];
    __shared__ float sx[QC][QC];    // x tile [q][p_local]

    for (int i = tid; i < QC * DSTATE; i += 256) {
        int q = i >> 4, n = i & 15;
        size_t base = (size_t)(t0 + q) * CONVDIM + DINNER;
        sB[q][n] = g_xbc[base + n];
        sC[q][n] = g_xbc[base + DSTATE + n];
    }
    if (tid < QC) sdt[tid] = g_dt[(t0 + tid) * NHEADS + h];
    __syncthreads();

    float A = -expf(A_log[h]);
    if (tid == 0) {
        float run = 0.f;
        for (int q = 0; q < QC; q++) { run += sdt[q] * A; scs[q] = run; }
    }
    __syncthreads();
    if (tid < QC) g_cs[(t0 + tid) * NHEADS + h] = scs[tid];

    float cl = scs[QC - 1];
    for (int i = tid; i < QC * DSTATE; i += 256) {
        int q = i >> 4, n = i & 15;
        sE[q][n] = sB[q][n] * expf(cl - scs[q]) * sdt[q];
    }
    for (int i = tid; i < QC * QC; i += 256) {
        int q = i >> 6, s = i & 63;
        float v = 0.f;
        if (s <= q) {
            float d = 0.f;
            #pragma unroll
            for (int n = 0; n < DSTATE; n++) d += sC[q][n] * sB[s][n];
            v = expf(scs[q] - scs[s]) * d * sdt[s];
        }
        sMt[s][q] = v;
    }
    __syncthreads();

    float Dh = Dp[h];
    int q0 = (tid >> 4) * 4;     // Y microtile q base
    int p0 = (tid & 15) * 4;     // Y microtile p base (within 64-tile)
    int pS = tid >> 2;           // states: p index (0..63 within tile)
    int n0 = (tid & 3) * 4;      // states: n base

    for (int pt = 0; pt < 4; pt++) {
        int pbase = pt * QC;
        for (int i = tid; i < QC * QC; i += 256) {
            int q = i >> 6, pl = i & 63;
            sx[q][pl] = g_xbc[(size_t)(t0 + q) * CONVDIM + h * HEADDIM + pbase + pl];
        }
        __syncthreads();

        // Y_diag: acc[q0..q0+3][p0..p0+3] = sum_s M[q][s] * x[s][p] * dt[s]
        float acc[4][4];
        #pragma unroll
        for (int i = 0; i < 4; i++)
            #pragma unroll
            for (int j = 0; j < 4; j++) acc[i][j] = 0.f;

        for (int s = 0; s < QC; s++) {
            float4 m4 = *(const float4*)&sMt[s][q0];
            float4 x4 = *(const float4*)&sx[s][p0];
            float mv[4] = {m4.x, m4.y, m4.z, m4.w};
            float xv[4] = {x4.x, x4.y, x4.z, x4.w};
            #pragma unroll
            for (int i = 0; i < 4; i++)
                #pragma unroll
                for (int j = 0; j < 4; j++)
                    acc[i][j] += mv[i] * xv[j];
        }
        #pragma unroll
        for (int i = 0; i < 4; i++) {
            int q = q0 + i;
            float4 o;
            o.x = acc[i][0] + Dh * sx[q][p0 + 0];
            o.y = acc[i][1] + Dh * sx[q][p0 + 1];
            o.z = acc[i][2] + Dh * sx[q][p0 + 2];
            o.w = acc[i][3] + Dh * sx[q][p0 + 3];
            *(float4*)&g_y[(size_t)(t0 + q) * DINNER + h * HEADDIM + pbase + p0] = o;
        }

        // states[p][n] = sum_q E[q][n] * x[q][p]
        float accS[4] = {0.f, 0.f, 0.f, 0.f};
        for (int q = 0; q < QC; q++) {
            float xs = sx[q][pS];
            float4 e4 = *(const float4*)&sE[q][n0];
            accS[0] += e4.x * xs;
            accS[1] += e4.y * xs;
            accS[2] += e4.z * xs;
            accS[3] += e4.w * xs;
        }
        size_t sb = ((size_t)((b * NCHUNK + c) * NHEADS + h)) * HEADDIM * DSTATE
                    + (size_t)(pbase + pS) * DSTATE + n0;
        *(float4*)&g_states[sb] = make_float4(accS[0], accS[1], accS[2], accS[3]);
        __syncthreads();
    }
}

// ---------------- inter-chunk scan: prev[c] = state entering chunk c --------
__global__ void __launch_bounds__(512) scan_kernel() {
    int pb = blockIdx.x, h = blockIdx.y, b = blockIdx.z;
    int tid = threadIdx.x;            // 512 = 32 p * 16 n
    int pl = tid >> 4, n = tid & 15;
    int p = pb * 32 + pl;
    float carry = 0.f;
    for (int c = 0; c < NCHUNK; c++) {
        size_t idx = ((size_t)((b * NCHUNK + c) * NHEADS + h)) * HEADDIM * DSTATE
                     + (size_t)p * DSTATE + n;
        g_prev[idx] = carry;
        float dec = expf(g_cs[(b * SEQLEN + c * QC + QC - 1) * NHEADS + h]);
        carry = dec * carry + g_states[idx];
    }
}

// ---------------- Y_off: g_y += exp(cs[q]) * C[q,:] . prev[p,:] -------------
__global__ void __launch_bounds__(256) yoff_kernel() {
    int h = blockIdx.x, c = blockIdx.y, b = blockIdx.z;
    int t0 = b * SEQLEN + c * QC;
    int tid = threadIdx.x;

    __shared__ float sPrev[HEADDIM][DSTATE + 1];  // pad: kill stride-16 conflicts
    __shared__ float sC2[QC][DSTATE];
    __shared__ float sExp[QC];

    size_t pbase = ((size_t)((b * NCHUNK + c) * NHEADS + h)) * HEADDIM * DSTATE;
    for (int i = tid; i < HEADDIM * DSTATE; i += 256)
        sPrev[i >> 4][i & 15] = g_prev[pbase + i];
    for (int i = tid; i < QC * DSTATE; i += 256) {
        int q = i >> 4, n = i & 15;
        sC2[q][n] = g_xbc[(size_t)(t0 + q) * CONVDIM + DINNER + DSTATE + n];
    }
    if (tid < QC) sExp[tid] = expf(g_cs[(t0 + tid) * NHEADS + h]);
    __syncthreads();

    for (int i = tid; i < QC * HEADDIM; i += 256) {
        int q = i >> 8, p = i & 255;
        float d = 0.f;
        #pragma unroll
        for (int n = 0; n < DSTATE; n++) d += sC2[q][n] * sPrev[p][n];
        size_t yi = (size_t)(t0 + q) * DINNER + h * HEADDIM + p;
        g_y[yi] += sExp[q] * d;
    }
}

// ---------------- gate (silu(z)) + RMSNorm ----------------------------------
__global__ void __launch_bounds__(256) gate_norm_kernel(const float* __restrict__ norm_w) {
    int t = blockIdx.x, tid = threadIdx.x;
    __shared__ float red[256];
    float v[8];
    float ss = 0.f;
    #pragma unroll
    for (int r = 0; r < 8; r++) {
        int i = r * 256 + tid;
        float y = g_y[(size_t)t * DINNER + i];
        float z = g_zx[(size_t)t * DPROJ + i];
        float w = y * (z / (1.f + expf(-z)));
        v[r] = w;
        ss += w * w;
    }
    red[tid] = ss;
    __syncthreads();
    for (int s = 128; s > 0; s >>= 1) {
        if (tid < s) red[tid] += red[tid + s];
        __syncthreads();
    }
    float scale = rsqrtf(red[0] / (float)DINNER + 1e-5f);
    #pragma unroll
    for (int r = 0; r < 8; r++) {
        int i = r * 256 + tid;
        g_yn[(size_t)t * DINNER + i] = v[r] * scale * norm_w[i];
    }
}

// ---------------- launch ----------------------------------------------------
extern "C" void kernel_launch(void* const* d_in, const int* in_sizes, int n_in,
                              void* d_out, int out_size) {
    const float* u       = (const float*)d_in[0];
    const float* W_in    = (const float*)d_in[1];
    const float* conv_w  = (const float*)d_in[2];
    const float* conv_b  = (const float*)d_in[3];
    const float* dt_bias = (const float*)d_in[4];
    const float* A_log   = (const float*)d_in[5];
    const float* Dv      = (const float*)d_in[6];
    const float* norm_w  = (const float*)d_in[7];
    const float* W_out   = (const float*)d_in[8];
    float* out = (float*)d_out;

    void* p;
    cudaGetSymbolAddress(&p, g_zx);  float* zx = (float*)p;
    cudaGetSymbolAddress(&p, g_yn);  float* yn = (float*)p;

    // 1) in-projection: [16384,1024] @ [1024,4136]
    sgemm_kernel<<<dim3((DPROJ + 127) / 128, NTOK / 128), 256>>>(
        NTOK, DPROJ, DMODEL, u, W_in, zx);

    // 2) dt softplus
    dt_kernel<<<(NTOK * NHEADS) / 256, 256>>>(dt_bias);

    // 3) causal depthwise conv + silu
    conv_silu_kernel<<<dim3((CONVDIM + 255) / 256, NTOK), 256>>>(conv_w, conv_b);

    // 4) per-chunk Y_diag + states
    chunk_kernel<<<dim3(NHEADS, NCHUNK, BATCH), 256>>>(A_log, Dv);

    // 5) inter-chunk scan
    scan_kernel<<<dim3(HEADDIM / 32, NHEADS, BATCH), 512>>>();

    // 6) Y_off accumulation
    yoff_kernel<<<dim3(NHEADS, NCHUNK, BATCH), 256>>>();

    // 7) gating + RMSNorm
    gate_norm_kernel<<<NTOK, 256>>>(norm_w);

    // 8) out-projection: [16384,2048] @ [2048,1024]
    sgemm_kernel<<<dim3(DMODEL / 128, NTOK / 128), 256>>>(
        NTOK, DMODEL, DINNER, yn, W_out, out);
}

// round 2
// speedup vs baseline: 2.9992x; 2.9992x over previous
#include <cuda_runtime.h>
#include <math.h>

#define BATCH   4
#define SEQLEN  4096
#define DMODEL  1024
#define DINNER  2048
#define DSTATE  16
#define NHEADS  8
#define HEADDIM 256
#define CONVDIM 2080            // DINNER + 2*DSTATE
#define DPROJ   4136            // 2*DINNER + 2*DSTATE + NHEADS
#define ZXS     4224            // padded stride for g_zx / g_Win (multiple of 128)
#define QC      64
#define NCHUNK  (SEQLEN/QC)     // 64
#define NTOK    (BATCH*SEQLEN)  // 16384

// ---------------- scratch (device globals: allocation-guard-safe) -----------
__device__ float g_zx[(size_t)NTOK * ZXS];          // in-proj output (z | xBC | dt_raw), padded
__device__ float g_Win[(size_t)DMODEL * ZXS];       // zero-padded W_in
__device__ float g_xbc[(size_t)NTOK * CONVDIM];     // conv+silu output
__device__ float g_dt[NTOK * NHEADS];               // softplus(dt)
__device__ float g_cs[NTOK * NHEADS];               // within-chunk cumsum of dt*A
__device__ float g_states[BATCH * NCHUNK * NHEADS * HEADDIM * DSTATE];
__device__ float g_prev[BATCH * NCHUNK * NHEADS * HEADDIM * DSTATE];
__device__ float g_y[(size_t)NTOK * DINNER];        // Y_diag (+D*x), then += Y_off
__device__ float g_yn[(size_t)NTOK * DINNER];       // gated + normalized

// ======================= tf32 tensor-core GEMM ==============================
// C[M,N] = A[M,K] @ B[K,N], all row-major fp32, tf32 MMA with fp32 accum.
// Requires: M % 128 == 0, N % 128 == 0, K % 32 == 0 (caller guarantees).
#define BM 128
#define BN 128
#define BKT 32
#define ASTR 36     // BKT + 4  (conflict-free A fragment loads)
#define BSTR 136    // BN  + 8  (conflict-free B fragment loads)
#define GEMM_SMEM ((2*BM*ASTR + 2*BKT*BSTR) * 4)

__device__ __forceinline__ unsigned f2tf(float f) {
    unsigned r;
    asm("cvt.rna.tf32.f32 %0, %1;" : "=r"(r) : "f"(f));
    return r;
}

__device__ __forceinline__ void cpa16(float* s, const float* gp) {
    unsigned saddr = (unsigned)__cvta_generic_to_shared(s);
    asm volatile("cp.async.cg.shared.global [%0], [%1], 16;" :: "r"(saddr), "l"(gp));
}

__device__ __forceinline__ void mma_tf32(float c[4], const unsigned a[4],
                                         unsigned b0, unsigned b1) {
    asm volatile(
        "mma.sync.aligned.m16n8k8.row.col.f32.tf32.tf32.f32 "
        "{%0,%1,%2,%3}, {%4,%5,%6,%7}, {%8,%9}, {%0,%1,%2,%3};"
        : "+f"(c[0]), "+f"(c[1]), "+f"(c[2]), "+f"(c[3])
        : "r"(a[0]), "r"(a[1]), "r"(a[2]), "r"(a[3]), "r"(b0), "r"(b1));
}

extern __shared__ float g_smem[];

__global__ void __launch_bounds__(256, 2)
mma_gemm(int M, int N, int K,
         const float* __restrict__ A, int lda,
         const float* __restrict__ B, int ldb,
         float* __restrict__ C, int ldc) {
    float* As = g_smem;                 // [2][BM][ASTR]
    float* Bs = g_smem + 2 * BM * ASTR; // [2][BKT][BSTR]

    int tid = threadIdx.x;
    int warp = tid >> 5, lane = tid & 31;
    int g = lane >> 2, tg = lane & 3;
    int warp_m = (warp >> 2) * 64;      // 2 warps along M
    int warp_n = (warp & 3) * 32;       // 4 warps along N

    int m0 = blockIdx.y * BM;
    int n0 = blockIdx.x * BN;

    int arow = tid >> 3;                // 0..31, +32*pass
    int acol = (tid & 7) * 4;
    int brow = tid >> 5;                // 0..7, +8*pass
    int bcol = (tid & 31) * 4;

    float acc[4][4][4];
    #pragma unroll
    for (int mi = 0; mi < 4; mi++)
        #pragma unroll
        for (int ni = 0; ni < 4; ni++)
            #pragma unroll
            for (int r = 0; r < 4; r++) acc[mi][ni][r] = 0.f;

    const int KT = K / BKT;

    auto load_tile = [&](int kt, int s) {
        const float* Ag = A + (size_t)m0 * lda + kt * BKT;
        float* Asb = As + s * BM * ASTR;
        #pragma unroll
        for (int p = 0; p < 4; p++) {
            int r = arow + p * 32;
            cpa16(&Asb[r * ASTR + acol], Ag + (size_t)r * lda + acol);
        }
        const float* Bg = B + (size_t)(kt * BKT) * ldb + n0;
        float* Bsb = Bs + s * BKT * BSTR;
        #pragma unroll
        for (int p = 0; p < 4; p++) {
            int r = brow + p * 8;
            cpa16(&Bsb[r * BSTR + bcol], Bg + (size_t)r * ldb + bcol);
        }
        asm volatile("cp.async.commit_group;");
    };

    load_tile(0, 0);

    for (int kt = 0; kt < KT; kt++) {
        int s = kt & 1;
        if (kt + 1 < KT) {
            load_tile(kt + 1, s ^ 1);
            asm volatile("cp.async.wait_group 1;");
        } else {
            asm volatile("cp.async.wait_group 0;");
        }
        __syncthreads();

        const float* Asb = As + s * BM * ASTR + (size_t)warp_m * ASTR;
        const float* Bsb = Bs + s * BKT * BSTR + warp_n;

        #pragma unroll
        for (int ks = 0; ks < 4; ks++) {
            int k0 = ks * 8;
            unsigned afr[4][4], bfr[4][2];
            #pragma unroll
            for (int mi = 0; mi < 4; mi++) {
                const float* ap = Asb + (mi * 16 + g) * ASTR + k0 + tg;
                afr[mi][0] = f2tf(ap[0]);
                afr[mi][2] = f2tf(ap[4]);
                afr[mi][1] = f2tf(ap[8 * ASTR]);
                afr[mi][3] = f2tf(ap[8 * ASTR + 4]);
            }
            #pragma unroll
            for (int ni = 0; ni < 4; ni++) {
                const float* bp = Bsb + (k0 + tg) * BSTR + ni * 8 + g;
                bfr[ni][0] = f2tf(bp[0]);
                bfr[ni][1] = f2tf(bp[4 * BSTR]);
            }
            #pragma unroll
            for (int mi = 0; mi < 4; mi++)
                #pragma unroll
                for (int ni = 0; ni < 4; ni++)
                    mma_tf32(acc[mi][ni], afr[mi], bfr[ni][0], bfr[ni][1]);
        }
        __syncthreads();
    }

    // epilogue
    #pragma unroll
    for (int mi = 0; mi < 4; mi++) {
        #pragma unroll
        for (int ni = 0; ni < 4; ni++) {
            int row = m0 + warp_m + mi * 16 + g;
            int col = n0 + warp_n + ni * 8 + tg * 2;
            float2 v0 = make_float2(acc[mi][ni][0], acc[mi][ni][1]);
            float2 v1 = make_float2(acc[mi][ni][2], acc[mi][ni][3]);
            *(float2*)&C[(size_t)row * ldc + col] = v0;
            *(float2*)&C[(size_t)(row + 8) * ldc + col] = v1;
        }
    }
}

// ---------------- pad W_in into g_Win [DMODEL][ZXS] -------------------------
__global__ void pad_win_kernel(const float* __restrict__ W_in) {
    int i = blockIdx.x * 256 + threadIdx.x;
    if (i >= DMODEL * ZXS) return;
    int r = i / ZXS, c = i - r * ZXS;
    g_Win[i] = (c < DPROJ) ? W_in[(size_t)r * DPROJ + c] : 0.f;
}

// ---------------- dt = softplus(raw + dt_bias) ------------------------------
__global__ void dt_kernel(const float* __restrict__ dt_bias) {
    int i = blockIdx.x * blockDim.x + threadIdx.x; // over NTOK*NHEADS
    int h = i & 7;
    int t = i >> 3;
    float v = g_zx[(size_t)t * ZXS + DINNER + CONVDIM + h] + dt_bias[h];
    g_dt[i] = (v > 20.f) ? v : log1pf(expf(v));
}

// ---------------- depthwise causal conv (width 4) + silu --------------------
__global__ void conv_silu_kernel(const float* __restrict__ conv_w,
                                 const float* __restrict__ conv_b) {
    int c = blockIdx.x * blockDim.x + threadIdx.x;
    int t = blockIdx.y;
    if (c >= CONVDIM) return;
    int tb = t & (SEQLEN - 1); // position within batch
    float acc = conv_b[c];
    #pragma unroll
    for (int k = 0; k < 4; k++) {
        int off = k - 3;
        if (tb + off >= 0)
            acc += g_zx[(size_t)(t + off) * ZXS + DINNER + c] * conv_w[c * 4 + k];
    }
    g_xbc[(size_t)t * CONVDIM + c] = acc / (1.f + expf(-acc));
}

// ---------------- per-chunk: cumsum, M=L*S*dt, Y_diag(+D*x), states ---------
__global__ void __launch_bounds__(256)
chunk_kernel(const float* __restrict__ A_log, const float* __restrict__ Dp) {
    int h = blockIdx.x, c = blockIdx.y, b = blockIdx.z;
    int t0 = b * SEQLEN + c * QC;
    int tid = threadIdx.x;

    __shared__ float sB[QC][DSTATE];
    __shared__ float sC[QC][DSTATE];
    __shared__ float sdt[QC], scs[QC];
    __shared__ float sMt[QC][QC];   // transposed: sMt[s][q] = M[q][s]
    __shared__ float sE[QC][DSTATE];
    __shared__ float sx[QC][QC];    // x tile [q][p_local]

    for (int i = tid; i < QC * DSTATE; i += 256) {
        int q = i >> 4, n = i & 15;
        size_t base = (size_t)(t0 + q) * CONVDIM + DINNER;
        sB[q][n] = g_xbc[base + n];
        sC[q][n] = g_xbc[base + DSTATE + n];
    }
    if (tid < QC) sdt[tid] = g_dt[(t0 + tid) * NHEADS + h];
    __syncthreads();

    float A = -expf(A_log[h]);
    if (tid == 0) {
        float run = 0.f;
        for (int q = 0; q < QC; q++) { run += sdt[q] * A; scs[q] = run; }
    }
    __syncthreads();
    if (tid < QC) g_cs[(t0 + tid) * NHEADS + h] = scs[tid];

    float cl = scs[QC - 1];
    for (int i = tid; i < QC * DSTATE; i += 256) {
        int q = i >> 4, n = i & 15;
        sE[q][n] = sB[q][n] * expf(cl - scs[q]) * sdt[q];
    }
    for (int i = tid; i < QC * QC; i += 256) {
        int q = i >> 6, s = i & 63;
        float v = 0.f;
        if (s <= q) {
            float d = 0.f;
            #pragma unroll
            for (int n = 0; n < DSTATE; n++) d += sC[q][n] * sB[s][n];
            v = expf(scs[q] - scs[s]) * d * sdt[s];
        }
        sMt[s][q] = v;
    }
    __syncthreads();

    float Dh = Dp[h];
    int q0 = (tid >> 4) * 4;     // Y microtile q base
    int p0 = (tid & 15) * 4;     // Y microtile p base (within 64-tile)
    int pS = tid >> 2;           // states: p index (0..63 within tile)
    int n0 = (tid & 3) * 4;      // states: n base

    for (int pt = 0; pt < 4; pt++) {
        int pbase = pt * QC;
        for (int i = tid; i < QC * QC; i += 256) {
            int q = i >> 6, pl = i & 63;
            sx[q][pl] = g_xbc[(size_t)(t0 + q) * CONVDIM + h * HEADDIM + pbase + pl];
        }
        __syncthreads();

        // Y_diag: acc[q0..q0+3][p0..p0+3] = sum_s M[q][s] * x[s][p]
        float acc[4][4];
        #pragma unroll
        for (int i = 0; i < 4; i++)
            #pragma unroll
            for (int j = 0; j < 4; j++) acc[i][j] = 0.f;

        for (int s = 0; s < QC; s++) {
            float4 m4 = *(const float4*)&sMt[s][q0];
            float4 x4 = *(const float4*)&sx[s][p0];
            float mv[4] = {m4.x, m4.y, m4.z, m4.w};
            float xv[4] = {x4.x, x4.y, x4.z, x4.w};
            #pragma unroll
            for (int i = 0; i < 4; i++)
                #pragma unroll
                for (int j = 0; j < 4; j++)
                    acc[i][j] += mv[i] * xv[j];
        }
        #pragma unroll
        for (int i = 0; i < 4; i++) {
            int q = q0 + i;
            float4 o;
            o.x = acc[i][0] + Dh * sx[q][p0 + 0];
            o.y = acc[i][1] + Dh * sx[q][p0 + 1];
            o.z = acc[i][2] + Dh * sx[q][p0 + 2];
            o.w = acc[i][3] + Dh * sx[q][p0 + 3];
            *(float4*)&g_y[(size_t)(t0 + q) * DINNER + h * HEADDIM + pbase + p0] = o;
        }

        // states[p][n] = sum_q E[q][n] * x[q][p]
        float accS[4] = {0.f, 0.f, 0.f, 0.f};
        for (int q = 0; q < QC; q++) {
            float xs = sx[q][pS];
            float4 e4 = *(const float4*)&sE[q][n0];
            accS[0] += e4.x * xs;
            accS[1] += e4.y * xs;
            accS[2] += e4.z * xs;
            accS[3] += e4.w * xs;
        }
        size_t sb = ((size_t)((b * NCHUNK + c) * NHEADS + h)) * HEADDIM * DSTATE
                    + (size_t)(pbase + pS) * DSTATE + n0;
        *(float4*)&g_states[sb] = make_float4(accS[0], accS[1], accS[2], accS[3]);
        __syncthreads();
    }
}

// ---------------- inter-chunk scan: prev[c] = state entering chunk c --------
__global__ void __launch_bounds__(512) scan_kernel() {
    int pb = blockIdx.x, h = blockIdx.y, b = blockIdx.z;
    int tid = threadIdx.x;            // 512 = 32 p * 16 n
    int pl = tid >> 4, n = tid & 15;
    int p = pb * 32 + pl;
    float carry = 0.f;
    for (int c = 0; c < NCHUNK; c++) {
        size_t idx = ((size_t)((b * NCHUNK + c) * NHEADS + h)) * HEADDIM * DSTATE
                     + (size_t)p * DSTATE + n;
        g_prev[idx] = carry;
        float dec = expf(g_cs[(b * SEQLEN + c * QC + QC - 1) * NHEADS + h]);
        carry = dec * carry + g_states[idx];
    }
}

// ---------------- Y_off: g_y += exp(cs[q]) * C[q,:] . prev[p,:] -------------
__global__ void __launch_bounds__(256) yoff_kernel() {
    int h = blockIdx.x, c = blockIdx.y, b = blockIdx.z;
    int t0 = b * SEQLEN + c * QC;
    int tid = threadIdx.x;

    __shared__ float sPrev[HEADDIM][DSTATE + 1];  // pad: kill stride-16 conflicts
    __shared__ float sC2[QC][DSTATE];
    __shared__ float sExp[QC];

    size_t pbase = ((size_t)((b * NCHUNK + c) * NHEADS + h)) * HEADDIM * DSTATE;
    for (int i = tid; i < HEADDIM * DSTATE; i += 256)
        sPrev[i >> 4][i & 15] = g_prev[pbase + i];
    for (int i = tid; i < QC * DSTATE; i += 256) {
        int q = i >> 4, n = i & 15;
        sC2[q][n] = g_xbc[(size_t)(t0 + q) * CONVDIM + DINNER + DSTATE + n];
    }
    if (tid < QC) sExp[tid] = expf(g_cs[(t0 + tid) * NHEADS + h]);
    __syncthreads();

    for (int i = tid; i < QC * HEADDIM; i += 256) {
        int q = i >> 8, p = i & 255;
        float d = 0.f;
        #pragma unroll
        for (int n = 0; n < DSTATE; n++) d += sC2[q][n] * sPrev[p][n];
        size_t yi = (size_t)(t0 + q) * DINNER + h * HEADDIM + p;
        g_y[yi] += sExp[q] * d;
    }
}

// ---------------- gate (silu(z)) + RMSNorm ----------------------------------
__global__ void __launch_bounds__(256) gate_norm_kernel(const float* __restrict__ norm_w) {
    int t = blockIdx.x, tid = threadIdx.x;
    __shared__ float red[256];
    float v[8];
    float ss = 0.f;
    #pragma unroll
    for (int r = 0; r < 8; r++) {
        int i = r * 256 + tid;
        float y = g_y[(size_t)t * DINNER + i];
        float z = g_zx[(size_t)t * ZXS + i];
        float w = y * (z / (1.f + expf(-z)));
        v[r] = w;
        ss += w * w;
    }
    red[tid] = ss;
    __syncthreads();
    for (int s = 128; s > 0; s >>= 1) {
        if (tid < s) red[tid] += red[tid + s];
        __syncthreads();
    }
    float scale = rsqrtf(red[0] / (float)DINNER + 1e-5f);
    #pragma unroll
    for (int r = 0; r < 8; r++) {
        int i = r * 256 + tid;
        g_yn[(size_t)t * DINNER + i] = v[r] * scale * norm_w[i];
    }
}

// ---------------- launch ----------------------------------------------------
extern "C" void kernel_launch(void* const* d_in, const int* in_sizes, int n_in,
                              void* d_out, int out_size) {
    const float* u       = (const float*)d_in[0];
    const float* W_in    = (const float*)d_in[1];
    const float* conv_w  = (const float*)d_in[2];
    const float* conv_b  = (const float*)d_in[3];
    const float* dt_bias = (const float*)d_in[4];
    const float* A_log   = (const float*)d_in[5];
    const float* Dv      = (const float*)d_in[6];
    const float* norm_w  = (const float*)d_in[7];
    const float* W_out   = (const float*)d_in[8];
    float* out = (float*)d_out;

    void* p;
    cudaGetSymbolAddress(&p, g_zx);  float* zx  = (float*)p;
    cudaGetSymbolAddress(&p, g_Win); float* win = (float*)p;
    cudaGetSymbolAddress(&p, g_yn);  float* yn  = (float*)p;

    cudaFuncSetAttribute(mma_gemm, cudaFuncAttributeMaxDynamicSharedMemorySize, GEMM_SMEM);

    // 0) pad W_in
    pad_win_kernel<<<(DMODEL * ZXS + 255) / 256, 256>>>(W_in);

    // 1) in-projection: [16384,1024] @ [1024,4224(padded)]
    mma_gemm<<<dim3(ZXS / BN, NTOK / BM), 256, GEMM_SMEM>>>(
        NTOK, ZXS, DMODEL, u, DMODEL, win, ZXS, zx, ZXS);

    // 2) dt softplus
    dt_kernel<<<(NTOK * NHEADS) / 256, 256>>>(dt_bias);

    // 3) causal depthwise conv + silu
    conv_silu_kernel<<<dim3((CONVDIM + 255) / 256, NTOK), 256>>>(conv_w, conv_b);

    // 4) per-chunk Y_diag + states
    chunk_kernel<<<dim3(NHEADS, NCHUNK, BATCH), 256>>>(A_log, Dv);

    // 5) inter-chunk scan
    scan_kernel<<<dim3(HEADDIM / 32, NHEADS, BATCH), 512>>>();

    // 6) Y_off accumulation
    yoff_kernel<<<dim3(NHEADS, NCHUNK, BATCH), 256>>>();

    // 7) gating + RMSNorm
    gate_norm_kernel<<<NTOK, 256>>>(norm_w);

    // 8) out-projection: [16384,2048] @ [2048,1024]
    mma_gemm<<<dim3(DMODEL / BN, NTOK / BM), 256, GEMM_SMEM>>>(
        NTOK, DMODEL, DINNER, yn, DINNER, W_out, DMODEL, out, DMODEL);
}

// round 3
// speedup vs baseline: 3.1542x; 1.0517x over previous
#include <cuda_runtime.h>
#include <math.h>

#define BATCH   4
#define SEQLEN  4096
#define DMODEL  1024
#define DINNER  2048
#define DSTATE  16
#define NHEADS  8
#define HEADDIM 256
#define CONVDIM 2080            // DINNER + 2*DSTATE
#define DPROJ   4136            // 2*DINNER + 2*DSTATE + NHEADS
#define ZXS     4224            // padded stride for g_zx / g_Win
#define QC      64
#define NCHUNK  (SEQLEN/QC)
#define NTOK    (BATCH*SEQLEN)

// ---------------- scratch ----------------------------------------------------
__device__ float g_zx[(size_t)NTOK * ZXS];          // in-proj output (z | xBC | dt_raw)
__device__ float g_Win[(size_t)DMODEL * ZXS];       // zero-padded W_in (tf32 bits)
__device__ float g_u32[(size_t)NTOK * DMODEL];      // u as tf32 bits
__device__ float g_Wout32[(size_t)DINNER * DMODEL]; // W_out as tf32 bits
__device__ float g_xbc[(size_t)NTOK * CONVDIM];     // conv+silu output
__device__ float g_cs[NTOK * NHEADS];               // within-chunk cumsum of dt*A
__device__ float g_states[BATCH * NCHUNK * NHEADS * HEADDIM * DSTATE];
__device__ float g_prev[BATCH * NCHUNK * NHEADS * HEADDIM * DSTATE];
__device__ float g_y[(size_t)NTOK * DINNER];        // Y_diag (+D*x), then += Y_off
__device__ float g_yn[(size_t)NTOK * DINNER];       // gated + normalized (tf32 bits)

// ======================= tf32 tensor-core GEMM ==============================
// Operands are PRE-CONVERTED tf32 bit patterns -> no cvt in the inner loop.
#define BM 128
#define BN 128
#define BKT 32
#define ASTR 36
#define BSTR 136
#define GEMM_SMEM ((2*BM*ASTR + 2*BKT*BSTR) * 4)

__device__ __forceinline__ unsigned f2tf(float f) {
    unsigned r;
    asm("cvt.rna.tf32.f32 %0, %1;" : "=r"(r) : "f"(f));
    return r;
}

__device__ __forceinline__ void cpa16(float* s, const float* gp) {
    unsigned saddr = (unsigned)__cvta_generic_to_shared(s);
    asm volatile("cp.async.cg.shared.global [%0], [%1], 16;" :: "r"(saddr), "l"(gp));
}

__device__ __forceinline__ void mma_tf32(float c[4], const unsigned a[4],
                                         unsigned b0, unsigned b1) {
    asm volatile(
        "mma.sync.aligned.m16n8k8.row.col.f32.tf32.tf32.f32 "
        "{%0,%1,%2,%3}, {%4,%5,%6,%7}, {%8,%9}, {%0,%1,%2,%3};"
        : "+f"(c[0]), "+f"(c[1]), "+f"(c[2]), "+f"(c[3])
        : "r"(a[0]), "r"(a[1]), "r"(a[2]), "r"(a[3]), "r"(b0), "r"(b1));
}

extern __shared__ float g_smem[];

__global__ void __launch_bounds__(256, 2)
mma_gemm(int M, int N, int K,
         const float* __restrict__ A, int lda,
         const float* __restrict__ B, int ldb,
         float* __restrict__ C, int ldc) {
    float* As = g_smem;                 // [2][BM][ASTR]
    float* Bs = g_smem + 2 * BM * ASTR; // [2][BKT][BSTR]

    int tid = threadIdx.x;
    int warp = tid >> 5, lane = tid & 31;
    int g = lane >> 2, tg = lane & 3;
    int warp_m = (warp >> 2) * 64;
    int warp_n = (warp & 3) * 32;

    int m0 = blockIdx.y * BM;
    int n0 = blockIdx.x * BN;

    int arow = tid >> 3;
    int acol = (tid & 7) * 4;
    int brow = tid >> 5;
    int bcol = (tid & 31) * 4;

    float acc[4][4][4];
    #pragma unroll
    for (int mi = 0; mi < 4; mi++)
        #pragma unroll
        for (int ni = 0; ni < 4; ni++)
            #pragma unroll
            for (int r = 0; r < 4; r++) acc[mi][ni][r] = 0.f;

    const int KT = K / BKT;

    auto load_tile = [&](int kt, int s) {
        const float* Ag = A + (size_t)m0 * lda + kt * BKT;
        float* Asb = As + s * BM * ASTR;
        #pragma unroll
        for (int p = 0; p < 4; p++) {
            int r = arow + p * 32;
            cpa16(&Asb[r * ASTR + acol], Ag + (size_t)r * lda + acol);
        }
        const float* Bg = B + (size_t)(kt * BKT) * ldb + n0;
        float* Bsb = Bs + s * BKT * BSTR;
        #pragma unroll
        for (int p = 0; p < 4; p++) {
            int r = brow + p * 8;
            cpa16(&Bsb[r * BSTR + bcol], Bg + (size_t)r * ldb + bcol);
        }
        asm volatile("cp.async.commit_group;");
    };

    load_tile(0, 0);

    for (int kt = 0; kt < KT; kt++) {
        int s = kt & 1;
        if (kt + 1 < KT) {
            load_tile(kt + 1, s ^ 1);
            asm volatile("cp.async.wait_group 1;");
        } else {
            asm volatile("cp.async.wait_group 0;");
        }
        __syncthreads();

        const float* Asb = As + s * BM * ASTR + (size_t)warp_m * ASTR;
        const float* Bsb = Bs + s * BKT * BSTR + warp_n;

        #pragma unroll
        for (int ks = 0; ks < 4; ks++) {
            int k0 = ks * 8;
            unsigned afr[4][4], bfr[4][2];
            #pragma unroll
            for (int mi = 0; mi < 4; mi++) {
                const float* ap = Asb + (mi * 16 + g) * ASTR + k0 + tg;
                afr[mi][0] = __float_as_uint(ap[0]);
                afr[mi][2] = __float_as_uint(ap[4]);
                afr[mi][1] = __float_as_uint(ap[8 * ASTR]);
                afr[mi][3] = __float_as_uint(ap[8 * ASTR + 4]);
            }
            #pragma unroll
            for (int ni = 0; ni < 4; ni++) {
                const float* bp = Bsb + (k0 + tg) * BSTR + ni * 8 + g;
                bfr[ni][0] = __float_as_uint(bp[0]);
                bfr[ni][1] = __float_as_uint(bp[4 * BSTR]);
            }
            #pragma unroll
            for (int mi = 0; mi < 4; mi++)
                #pragma unroll
                for (int ni = 0; ni < 4; ni++)
                    mma_tf32(acc[mi][ni], afr[mi], bfr[ni][0], bfr[ni][1]);
        }
        __syncthreads();
    }

    #pragma unroll
    for (int mi = 0; mi < 4; mi++) {
        #pragma unroll
        for (int ni = 0; ni < 4; ni++) {
            int row = m0 + warp_m + mi * 16 + g;
            int col = n0 + warp_n + ni * 8 + tg * 2;
            float2 v0 = make_float2(acc[mi][ni][0], acc[mi][ni][1]);
            float2 v1 = make_float2(acc[mi][ni][2], acc[mi][ni][3]);
            *(float2*)&C[(size_t)row * ldc + col] = v0;
            *(float2*)&C[(size_t)(row + 8) * ldc + col] = v1;
        }
    }
}

// ---------------- prepass: fp32 -> tf32 bits (vectorized) -------------------
__global__ void cvt_tf32_kernel(const float* __restrict__ src, float* __restrict__ dst,
                                int n4) {
    int i = blockIdx.x * 256 + threadIdx.x;
    if (i >= n4) return;
    float4 v = ((const float4*)src)[i];
    float4 o;
    o.x = __uint_as_float(f2tf(v.x));
    o.y = __uint_as_float(f2tf(v.y));
    o.z = __uint_as_float(f2tf(v.z));
    o.w = __uint_as_float(f2tf(v.w));
    ((float4*)dst)[i] = o;
}

// ---------------- pad W_in into g_Win [DMODEL][ZXS] as tf32 bits ------------
__global__ void pad_win_kernel(const float* __restrict__ W_in) {
    int i = blockIdx.x * 256 + threadIdx.x;
    if (i >= DMODEL * ZXS) return;
    int r = i / ZXS, c = i - r * ZXS;
    g_Win[i] = (c < DPROJ) ? __uint_as_float(f2tf(W_in[(size_t)r * DPROJ + c])) : 0.f;
}

// ---------------- tiled depthwise causal conv (width 4) + silu --------------
#define CT_T 64
#define CT_C 128
__global__ void __launch_bounds__(256)
conv_silu_kernel(const float* __restrict__ conv_w, const float* __restrict__ conv_b) {
    __shared__ float sx[CT_T + 3][CT_C];
    int c0 = blockIdx.x * CT_C;
    int t0 = blockIdx.y * CT_T;
    int tid = threadIdx.x;
    bool bstart = ((t0 & (SEQLEN - 1)) == 0);

    for (int i = tid; i < (CT_T + 3) * CT_C; i += 256) {
        int r = i / CT_C, cl = i - r * CT_C;
        int c = c0 + cl;
        float v = 0.f;
        if (c < CONVDIM && !(bstart && r < 3))
            v = g_zx[(size_t)(t0 - 3 + r) * ZXS + DINNER + c];
        sx[r][cl] = v;
    }
    __syncthreads();

    int cl = tid & (CT_C - 1);
    int tbase = (tid >> 7) * (CT_T / 2);
    int c = c0 + cl;
    if (c >= CONVDIM) return;
    float w0 = conv_w[c * 4 + 0], w1 = conv_w[c * 4 + 1];
    float w2 = conv_w[c * 4 + 2], w3 = conv_w[c * 4 + 3];
    float bb = conv_b[c];
    #pragma unroll 8
    for (int i = 0; i < CT_T / 2; i++) {
        int tl = tbase + i;
        float a = bb + sx[tl][cl] * w0 + sx[tl + 1][cl] * w1
                     + sx[tl + 2][cl] * w2 + sx[tl + 3][cl] * w3;
        g_xbc[(size_t)(t0 + tl) * CONVDIM + c] = a / (1.f + __expf(-a));
    }
}

// ---------------- per-chunk: dt, cumsum, M, Y_diag(+D*x), states ------------
__global__ void __launch_bounds__(256)
chunk_kernel(const float* __restrict__ A_log, const float* __restrict__ Dp,
             const float* __restrict__ dt_bias) {
    int h = blockIdx.x, c = blockIdx.y, b = blockIdx.z;
    int t0 = b * SEQLEN + c * QC;
    int tid = threadIdx.x;

    __shared__ float sB[QC][DSTATE];
    __shared__ float sC[QC][DSTATE];
    __shared__ float sdt[QC], scs[QC];
    __shared__ float sMt[QC][QC];
    __shared__ float sE[QC][DSTATE];
    __shared__ float sx[QC][QC];

    for (int i = tid; i < QC * DSTATE; i += 256) {
        int q = i >> 4, n = i & 15;
        size_t base = (size_t)(t0 + q) * CONVDIM + DINNER;
        sB[q][n] = g_xbc[base + n];
        sC[q][n] = g_xbc[base + DSTATE + n];
    }
    if (tid < QC) {
        float v = g_zx[(size_t)(t0 + tid) * ZXS + DINNER + CONVDIM + h] + dt_bias[h];
        sdt[tid] = (v > 20.f) ? v : log1pf(expf(v));
    }
    __syncthreads();

    float A = -expf(A_log[h]);
    if (tid == 0) {
        float run = 0.f;
        for (int q = 0; q < QC; q++) { run += sdt[q] * A; scs[q] = run; }
    }
    __syncthreads();
    if (tid < QC) g_cs[(t0 + tid) * NHEADS + h] = scs[tid];

    float cl = scs[QC - 1];
    for (int i = tid; i < QC * DSTATE; i += 256) {
        int q = i >> 4, n = i & 15;
        sE[q][n] = sB[q][n] * __expf(cl - scs[q]) * sdt[q];
    }
    for (int i = tid; i < QC * QC; i += 256) {
        int q = i >> 6, s = i & 63;
        float v = 0.f;
        if (s <= q) {
            float d = 0.f;
            #pragma unroll
            for (int n = 0; n < DSTATE; n++) d += sC[q][n] * sB[s][n];
            v = __expf(scs[q] - scs[s]) * d * sdt[s];
        }
        sMt[s][q] = v;
    }
    __syncthreads();

    float Dh = Dp[h];
    int q0 = (tid >> 4) * 4;
    int p0 = (tid & 15) * 4;
    int pS = tid >> 2;
    int n0 = (tid & 3) * 4;

    for (int pt = 0; pt < 4; pt++) {
        int pbase = pt * QC;
        for (int i = tid; i < QC * QC; i += 256) {
            int q = i >> 6, pl = i & 63;
            sx[q][pl] = g_xbc[(size_t)(t0 + q) * CONVDIM + h * HEADDIM + pbase + pl];
        }
        __syncthreads();

        float acc[4][4];
        #pragma unroll
        for (int i = 0; i < 4; i++)
            #pragma unroll
            for (int j = 0; j < 4; j++) acc[i][j] = 0.f;

        for (int s = 0; s < QC; s++) {
            float4 m4 = *(const float4*)&sMt[s][q0];
            float4 x4 = *(const float4*)&sx[s][p0];
            float mv[4] = {m4.x, m4.y, m4.z, m4.w};
            float xv[4] = {x4.x, x4.y, x4.z, x4.w};
            #pragma unroll
            for (int i = 0; i < 4; i++)
                #pragma unroll
                for (int j = 0; j < 4; j++)
                    acc[i][j] += mv[i] * xv[j];
        }
        #pragma unroll
        for (int i = 0; i < 4; i++) {
            int q = q0 + i;
            float4 o;
            o.x = acc[i][0] + Dh * sx[q][p0 + 0];
            o.y = acc[i][1] + Dh * sx[q][p0 + 1];
            o.z = acc[i][2] + Dh * sx[q][p0 + 2];
            o.w = acc[i][3] + Dh * sx[q][p0 + 3];
            *(float4*)&g_y[(size_t)(t0 + q) * DINNER + h * HEADDIM + pbase + p0] = o;
        }

        float accS[4] = {0.f, 0.f, 0.f, 0.f};
        for (int q = 0; q < QC; q++) {
            float xs = sx[q][pS];
            float4 e4 = *(const float4*)&sE[q][n0];
            accS[0] += e4.x * xs;
            accS[1] += e4.y * xs;
            accS[2] += e4.z * xs;
            accS[3] += e4.w * xs;
        }
        size_t sb = ((size_t)((b * NCHUNK + c) * NHEADS + h)) * HEADDIM * DSTATE
                    + (size_t)(pbase + pS) * DSTATE + n0;
        *(float4*)&g_states[sb] = make_float4(accS[0], accS[1], accS[2], accS[3]);
        __syncthreads();
    }
}

// ---------------- inter-chunk scan ------------------------------------------
__global__ void __launch_bounds__(512) scan_kernel() {
    int pb = blockIdx.x, h = blockIdx.y, b = blockIdx.z;
    int tid = threadIdx.x;
    int pl = tid >> 4, n = tid & 15;
    int p = pb * 32 + pl;
    float carry = 0.f;
    for (int c = 0; c < NCHUNK; c++) {
        size_t idx = ((size_t)((b * NCHUNK + c) * NHEADS + h)) * HEADDIM * DSTATE
                     + (size_t)p * DSTATE + n;
        g_prev[idx] = carry;
        float dec = __expf(g_cs[(b * SEQLEN + c * QC + QC - 1) * NHEADS + h]);
        carry = dec * carry + g_states[idx];
    }
}

// ---------------- Y_off ------------------------------------------------------
__global__ void __launch_bounds__(256) yoff_kernel() {
    int h = blockIdx.x, c = blockIdx.y, b = blockIdx.z;
    int t0 = b * SEQLEN + c * QC;
    int tid = threadIdx.x;

    __shared__ float sPrev[HEADDIM][DSTATE + 1];
    __shared__ float sC2[QC][DSTATE];
    __shared__ float sExp[QC];

    size_t pbase = ((size_t)((b * NCHUNK + c) * NHEADS + h)) * HEADDIM * DSTATE;
    for (int i = tid; i < HEADDIM * DSTATE; i += 256)
        sPrev[i >> 4][i & 15] = g_prev[pbase + i];
    for (int i = tid; i < QC * DSTATE; i += 256) {
        int q = i >> 4, n = i & 15;
        sC2[q][n] = g_xbc[(size_t)(t0 + q) * CONVDIM + DINNER + DSTATE + n];
    }
    if (tid < QC) sExp[tid] = __expf(g_cs[(t0 + tid) * NHEADS + h]);
    __syncthreads();

    for (int i = tid; i < QC * HEADDIM; i += 256) {
        int q = i >> 8, p = i & 255;
        float d = 0.f;
        #pragma unroll
        for (int n = 0; n < DSTATE; n++) d += sC2[q][n] * sPrev[p][n];
        size_t yi = (size_t)(t0 + q) * DINNER + h * HEADDIM + p;
        g_y[yi] += sExp[q] * d;
    }
}

// ---------------- gate (silu(z)) + RMSNorm -> tf32 bits ---------------------
__global__ void __launch_bounds__(256) gate_norm_kernel(const float* __restrict__ norm_w) {
    int t = blockIdx.x, tid = threadIdx.x;
    __shared__ float red[256];
    float v[8];
    float ss = 0.f;
    #pragma unroll
    for (int r = 0; r < 8; r++) {
        int i = r * 256 + tid;
        float y = g_y[(size_t)t * DINNER + i];
        float z = g_zx[(size_t)t * ZXS + i];
        float w = y * (z / (1.f + __expf(-z)));
        v[r] = w;
        ss += w * w;
    }
    red[tid] = ss;
    __syncthreads();
    for (int s = 128; s > 0; s >>= 1) {
        if (tid < s) red[tid] += red[tid + s];
        __syncthreads();
    }
    float scale = rsqrtf(red[0] / (float)DINNER + 1e-5f);
    #pragma unroll
    for (int r = 0; r < 8; r++) {
        int i = r * 256 + tid;
        g_yn[(size_t)t * DINNER + i] = __uint_as_float(f2tf(v[r] * scale * norm_w[i]));
    }
}

// ---------------- launch ----------------------------------------------------
extern "C" void kernel_launch(void* const* d_in, const int* in_sizes, int n_in,
                              void* d_out, int out_size) {
    const float* u       = (const float*)d_in[0];
    const float* W_in    = (const float*)d_in[1];
    const float* conv_w  = (const float*)d_in[2];
    const float* conv_b  = (const float*)d_in[3];
    const float* dt_bias = (const float*)d_in[4];
    const float* A_log   = (const float*)d_in[5];
    const float* Dv      = (const float*)d_in[6];
    const float* norm_w  = (const float*)d_in[7];
    const float* W_out   = (const float*)d_in[8];
    float* out = (float*)d_out;

    void* p;
    cudaGetSymbolAddress(&p, g_zx);     float* zx  = (float*)p;
    cudaGetSymbolAddress(&p, g_Win);    float* win = (float*)p;
    cudaGetSymbolAddress(&p, g_u32);    float* u32 = (float*)p;
    cudaGetSymbolAddress(&p, g_Wout32); float* wo32 = (float*)p;
    cudaGetSymbolAddress(&p, g_yn);     float* yn  = (float*)p;

    cudaFuncSetAttribute(mma_gemm, cudaFuncAttributeMaxDynamicSharedMemorySize, GEMM_SMEM);

    // prepasses: tf32 conversion of GEMM operands
    pad_win_kernel<<<(DMODEL * ZXS + 255) / 256, 256>>>(W_in);
    cvt_tf32_kernel<<<((NTOK * DMODEL / 4) + 255) / 256, 256>>>(u, u32, NTOK * DMODEL / 4);
    cvt_tf32_kernel<<<((DINNER * DMODEL / 4) + 255) / 256, 256>>>(W_out, wo32, DINNER * DMODEL / 4);

    // 1) in-projection
    mma_gemm<<<dim3(ZXS / BN, NTOK / BM), 256, GEMM_SMEM>>>(
        NTOK, ZXS, DMODEL, u32, DMODEL, win, ZXS, zx, ZXS);

    // 2) conv + silu (tiled)
    conv_silu_kernel<<<dim3((CONVDIM + CT_C - 1) / CT_C, NTOK / CT_T), 256>>>(conv_w, conv_b);

    // 3) per-chunk (dt folded in)
    chunk_kernel<<<dim3(NHEADS, NCHUNK, BATCH), 256>>>(A_log, Dv, dt_bias);

    // 4) inter-chunk scan
    scan_kernel<<<dim3(HEADDIM / 32, NHEADS, BATCH), 512>>>();

    // 5) Y_off
    yoff_kernel<<<dim3(NHEADS, NCHUNK, BATCH), 256>>>();

    // 6) gating + RMSNorm (emits tf32 bits)
    gate_norm_kernel<<<NTOK, 256>>>(norm_w);

    // 7) out-projection
    mma_gemm<<<dim3(DMODEL / BN, NTOK / BM), 256, GEMM_SMEM>>>(
        NTOK, DMODEL, DINNER, yn, DINNER, wo32, DMODEL, out, DMODEL);
}

// round 5
// speedup vs baseline: 3.2016x; 1.0150x over previous
#include <cuda_runtime.h>
#include <math.h>
#include <stdint.h>

#define BATCH   4
#define SEQLEN  4096
#define DMODEL  1024
#define DINNER  2048
#define DSTATE  16
#define NHEADS  8
#define HEADDIM 256
#define CONVDIM 2080
#define DPROJ   4136
#define ZXS     4224
#define QC      64
#define NCHUNK  (SEQLEN/QC)
#define NTOK    (BATCH*SEQLEN)

// ---------------- scratch ----------------------------------------------------
__device__ float g_zx[(size_t)NTOK * ZXS];          // in-proj output (z | xBC | dt_raw)
__device__ float g_Win[(size_t)DMODEL * ZXS];       // zero-padded W_in (tf32 bits)
__device__ float g_u32[(size_t)NTOK * DMODEL];      // u as tf32 bits
__device__ float g_Wout32[(size_t)DINNER * DMODEL]; // W_out as tf32 bits
__device__ float g_xbc[(size_t)NTOK * CONVDIM];
__device__ float g_cs[NTOK * NHEADS];
__device__ float g_states[BATCH * NCHUNK * NHEADS * HEADDIM * DSTATE];
__device__ float g_prev[BATCH * NCHUNK * NHEADS * HEADDIM * DSTATE];
__device__ float g_y[(size_t)NTOK * DINNER];
__device__ float g_yn[(size_t)NTOK * DINNER];       // gated+normalized (tf32 bits)

// ======================= tf32 tensor-core GEMM ==============================
// 128x128 block tile, 4 warps, 64x64 warp tile. Operands pre-converted tf32.
#define BM 128
#define BN 128
#define BKT 32
#define ASTR 36
#define BSTR 136
#define GEMM_SMEM ((2*BM*ASTR + 2*BKT*BSTR) * 4)

__device__ __forceinline__ unsigned f2tf(float f) {
    unsigned r;
    asm("cvt.rna.tf32.f32 %0, %1;" : "=r"(r) : "f"(f));
    return r;
}

__device__ __forceinline__ void cpa16(float* s, const float* gp) {
    unsigned saddr = (unsigned)__cvta_generic_to_shared(s);
    asm volatile("cp.async.cg.shared.global [%0], [%1], 16;" :: "r"(saddr), "l"(gp));
}

__device__ __forceinline__ void mma_tf32(float c[4], const unsigned a[4],
                                         unsigned b0, unsigned b1) {
    asm volatile(
        "mma.sync.aligned.m16n8k8.row.col.f32.tf32.tf32.f32 "
        "{%0,%1,%2,%3}, {%4,%5,%6,%7}, {%8,%9}, {%0,%1,%2,%3};"
        : "+f"(c[0]), "+f"(c[1]), "+f"(c[2]), "+f"(c[3])
        : "r"(a[0]), "r"(a[1]), "r"(a[2]), "r"(a[3]), "r"(b0), "r"(b1));
}

extern __shared__ float g_smem[];

__global__ void __launch_bounds__(128, 2)
mma_gemm(int M, int N, int K,
         const float* __restrict__ A, int lda,
         const float* __restrict__ B, int ldb,
         float* __restrict__ C, int ldc) {
    float* As = g_smem;                 // [2][BM][ASTR]
    float* Bs = g_smem + 2 * BM * ASTR; // [2][BKT][BSTR]

    int tid = threadIdx.x;
    int warp = tid >> 5, lane = tid & 31;
    int g = lane >> 2, tg = lane & 3;
    int warp_m = (warp >> 1) * 64;      // 2 warps along M
    int warp_n = (warp & 1) * 64;       // 2 warps along N

    int m0 = blockIdx.y * BM;
    int n0 = blockIdx.x * BN;

    float acc[4][8][4];
    #pragma unroll
    for (int mi = 0; mi < 4; mi++)
        #pragma unroll
        for (int ni = 0; ni < 8; ni++)
            #pragma unroll
            for (int r = 0; r < 4; r++) acc[mi][ni][r] = 0.f;

    const int KT = K / BKT;

    auto load_tile = [&](int kt, int s) {
        const float* Ag = A + (size_t)m0 * lda + kt * BKT;
        float* Asb = As + s * BM * ASTR;
        #pragma unroll
        for (int j = 0; j < 8; j++) {
            int id = tid + 128 * j;
            int r = id >> 3, c4 = (id & 7) * 4;
            cpa16(&Asb[r * ASTR + c4], Ag + (size_t)r * lda + c4);
        }
        const float* Bg = B + (size_t)(kt * BKT) * ldb + n0;
        float* Bsb = Bs + s * BKT * BSTR;
        #pragma unroll
        for (int j = 0; j < 8; j++) {
            int id = tid + 128 * j;
            int r = id >> 5, c4 = (id & 31) * 4;
            cpa16(&Bsb[r * BSTR + c4], Bg + (size_t)r * ldb + c4);
        }
        asm volatile("cp.async.commit_group;");
    };

    load_tile(0, 0);

    for (int kt = 0; kt < KT; kt++) {
        int s = kt & 1;
        if (kt + 1 < KT) {
            load_tile(kt + 1, s ^ 1);
            asm volatile("cp.async.wait_group 1;");
        } else {
            asm volatile("cp.async.wait_group 0;");
        }
        __syncthreads();

        const float* Asb = As + s * BM * ASTR + (size_t)warp_m * ASTR;
        const float* Bsb = Bs + s * BKT * BSTR + warp_n;

        #pragma unroll
        for (int ks = 0; ks < 4; ks++) {
            int k0 = ks * 8;
            unsigned afr[4][4], bfr[8][2];
            #pragma unroll
            for (int mi = 0; mi < 4; mi++) {
                const float* ap = Asb + (mi * 16 + g) * ASTR + k0 + tg;
                afr[mi][0] = __float_as_uint(ap[0]);
                afr[mi][2] = __float_as_uint(ap[4]);
                afr[mi][1] = __float_as_uint(ap[8 * ASTR]);
                afr[mi][3] = __float_as_uint(ap[8 * ASTR + 4]);
            }
            #pragma unroll
            for (int ni = 0; ni < 8; ni++) {
                const float* bp = Bsb + (k0 + tg) * BSTR + ni * 8 + g;
                bfr[ni][0] = __float_as_uint(bp[0]);
                bfr[ni][1] = __float_as_uint(bp[4 * BSTR]);
            }
            #pragma unroll
            for (int mi = 0; mi < 4; mi++)
                #pragma unroll
                for (int ni = 0; ni < 8; ni++)
                    mma_tf32(acc[mi][ni], afr[mi], bfr[ni][0], bfr[ni][1]);
        }
        __syncthreads();
    }

    #pragma unroll
    for (int mi = 0; mi < 4; mi++) {
        #pragma unroll
        for (int ni = 0; ni < 8; ni++) {
            int row = m0 + warp_m + mi * 16 + g;
            int col = n0 + warp_n + ni * 8 + tg * 2;
            float2 v0 = make_float2(acc[mi][ni][0], acc[mi][ni][1]);
            float2 v1 = make_float2(acc[mi][ni][2], acc[mi][ni][3]);
            *(float2*)&C[(size_t)row * ldc + col] = v0;
            *(float2*)&C[(size_t)(row + 8) * ldc + col] = v1;
        }
    }
}

// ---------------- prepass: fp32 -> tf32 bits --------------------------------
__global__ void cvt_tf32_kernel(const float* __restrict__ src, float* __restrict__ dst,
                                int n4) {
    int i = blockIdx.x * 256 + threadIdx.x;
    if (i >= n4) return;
    float4 v = ((const float4*)src)[i];
    float4 o;
    o.x = __uint_as_float(f2tf(v.x));
    o.y = __uint_as_float(f2tf(v.y));
    o.z = __uint_as_float(f2tf(v.z));
    o.w = __uint_as_float(f2tf(v.w));
    ((float4*)dst)[i] = o;
}

// ---------------- pad W_in into g_Win [DMODEL][ZXS] as tf32 bits ------------
__global__ void pad_win_kernel(const float* __restrict__ W_in) {
    int i = blockIdx.x * 256 + threadIdx.x;
    if (i >= DMODEL * ZXS) return;
    int r = i / ZXS, c = i - r * ZXS;
    g_Win[i] = (c < DPROJ) ? __uint_as_float(f2tf(W_in[(size_t)r * DPROJ + c])) : 0.f;
}

// ---------------- tiled depthwise causal conv + silu ------------------------
#define CT_T 64
#define CT_C 128
__global__ void __launch_bounds__(256)
conv_silu_kernel(const float* __restrict__ conv_w, const float* __restrict__ conv_b) {
    __shared__ float sx[CT_T + 3][CT_C];
    int c0 = blockIdx.x * CT_C;
    int t0 = blockIdx.y * CT_T;
    int tid = threadIdx.x;
    bool bstart = ((t0 & (SEQLEN - 1)) == 0);

    for (int i = tid; i < (CT_T + 3) * CT_C; i += 256) {
        int r = i / CT_C, cl = i - r * CT_C;
        int c = c0 + cl;
        float v = 0.f;
        if (c < CONVDIM && !(bstart && r < 3))
            v = g_zx[(size_t)(t0 - 3 + r) * ZXS + DINNER + c];
        sx[r][cl] = v;
    }
    __syncthreads();

    int cl = tid & (CT_C - 1);
    int tbase = (tid >> 7) * (CT_T / 2);
    int c = c0 + cl;
    if (c >= CONVDIM) return;
    float w0 = conv_w[c * 4 + 0], w1 = conv_w[c * 4 + 1];
    float w2 = conv_w[c * 4 + 2], w3 = conv_w[c * 4 + 3];
    float bb = conv_b[c];
    #pragma unroll 8
    for (int i = 0; i < CT_T / 2; i++) {
        int tl = tbase + i;
        float a = bb + sx[tl][cl] * w0 + sx[tl + 1][cl] * w1
                     + sx[tl + 2][cl] * w2 + sx[tl + 3][cl] * w3;
        g_xbc[(size_t)(t0 + tl) * CONVDIM + c] = a / (1.f + __expf(-a));
    }
}

// ---------------- per-chunk: dt, cumsum, M, Y_diag(+D*x), states ------------
__global__ void __launch_bounds__(256)
chunk_kernel(const float* __restrict__ A_log, const float* __restrict__ Dp,
             const float* __restrict__ dt_bias) {
    int h = blockIdx.x, c = blockIdx.y, b = blockIdx.z;
    int t0 = b * SEQLEN + c * QC;
    int tid = threadIdx.x;

    __shared__ float sB[QC][DSTATE];
    __shared__ float sC[QC][DSTATE];
    __shared__ float sdt[QC], scs[QC];
    __shared__ float sMt[QC][QC];
    __shared__ float sE[QC][DSTATE];
    __shared__ float sx[QC][QC];

    for (int i = tid; i < QC * DSTATE; i += 256) {
        int q = i >> 4, n = i & 15;
        size_t base = (size_t)(t0 + q) * CONVDIM + DINNER;
        sB[q][n] = g_xbc[base + n];
        sC[q][n] = g_xbc[base + DSTATE + n];
    }
    if (tid < QC) {
        float v = g_zx[(size_t)(t0 + tid) * ZXS + DINNER + CONVDIM + h] + dt_bias[h];
        sdt[tid] = (v > 20.f) ? v : log1pf(expf(v));
    }
    __syncthreads();

    float A = -expf(A_log[h]);
    if (tid == 0) {
        float run = 0.f;
        for (int q = 0; q < QC; q++) { run += sdt[q] * A; scs[q] = run; }
    }
    __syncthreads();
    if (tid < QC) g_cs[(t0 + tid) * NHEADS + h] = scs[tid];

    float cl = scs[QC - 1];
    for (int i = tid; i < QC * DSTATE; i += 256) {
        int q = i >> 4, n = i & 15;
        sE[q][n] = sB[q][n] * __expf(cl - scs[q]) * sdt[q];
    }
    for (int i = tid; i < QC * QC; i += 256) {
        int q = i >> 6, s = i & 63;
        float v = 0.f;
        if (s <= q) {
            float d = 0.f;
            #pragma unroll
            for (int n = 0; n < DSTATE; n++) d += sC[q][n] * sB[s][n];
            v = __expf(scs[q] - scs[s]) * d * sdt[s];
        }
        sMt[s][q] = v;
    }
    __syncthreads();

    float Dh = Dp[h];
    int q0 = (tid >> 4) * 4;
    int p0 = (tid & 15) * 4;
    int pS = tid >> 2;
    int n0 = (tid & 3) * 4;

    for (int pt = 0; pt < 4; pt++) {
        int pbase = pt * QC;
        for (int i = tid; i < QC * QC; i += 256) {
            int q = i >> 6, pl = i & 63;
            sx[q][pl] = g_xbc[(size_t)(t0 + q) * CONVDIM + h * HEADDIM + pbase + pl];
        }
        __syncthreads();

        float acc[4][4];
        #pragma unroll
        for (int i = 0; i < 4; i++)
            #pragma unroll
            for (int j = 0; j < 4; j++) acc[i][j] = 0.f;

        for (int s = 0; s < QC; s++) {
            float4 m4 = *(const float4*)&sMt[s][q0];
            float4 x4 = *(const float4*)&sx[s][p0];
            float mv[4] = {m4.x, m4.y, m4.z, m4.w};
            float xv[4] = {x4.x, x4.y, x4.z, x4.w};
            #pragma unroll
            for (int i = 0; i < 4; i++)
                #pragma unroll
                for (int j = 0; j < 4; j++)
                    acc[i][j] += mv[i] * xv[j];
        }
        #pragma unroll
        for (int i = 0; i < 4; i++) {
            int q = q0 + i;
            float4 o;
            o.x = acc[i][0] + Dh * sx[q][p0 + 0];
            o.y = acc[i][1] + Dh * sx[q][p0 + 1];
            o.z = acc[i][2] + Dh * sx[q][p0 + 2];
            o.w = acc[i][3] + Dh * sx[q][p0 + 3];
            *(float4*)&g_y[(size_t)(t0 + q) * DINNER + h * HEADDIM + pbase + p0] = o;
        }

        float accS[4] = {0.f, 0.f, 0.f, 0.f};
        for (int q = 0; q < QC; q++) {
            float xs = sx[q][pS];
            float4 e4 = *(const float4*)&sE[q][n0];
            accS[0] += e4.x * xs;
            accS[1] += e4.y * xs;
            accS[2] += e4.z * xs;
            accS[3] += e4.w * xs;
        }
        size_t sb = ((size_t)((b * NCHUNK + c) * NHEADS + h)) * HEADDIM * DSTATE
                    + (size_t)(pbase + pS) * DSTATE + n0;
        *(float4*)&g_states[sb] = make_float4(accS[0], accS[1], accS[2], accS[3]);
        __syncthreads();
    }
}

// ---------------- inter-chunk scan ------------------------------------------
__global__ void __launch_bounds__(512) scan_kernel() {
    int pb = blockIdx.x, h = blockIdx.y, b = blockIdx.z;
    int tid = threadIdx.x;
    int pl = tid >> 4, n = tid & 15;
    int p = pb * 32 + pl;
    float carry = 0.f;
    for (int c = 0; c < NCHUNK; c++) {
        size_t idx = ((size_t)((b * NCHUNK + c) * NHEADS + h)) * HEADDIM * DSTATE
                     + (size_t)p * DSTATE + n;
        g_prev[idx] = carry;
        float dec = __expf(g_cs[(b * SEQLEN + c * QC + QC - 1) * NHEADS + h]);
        carry = dec * carry + g_states[idx];
    }
}

// ---------------- Y_off ------------------------------------------------------
__global__ void __launch_bounds__(256) yoff_kernel() {
    int h = blockIdx.x, c = blockIdx.y, b = blockIdx.z;
    int t0 = b * SEQLEN + c * QC;
    int tid = threadIdx.x;

    __shared__ float sPrev[HEADDIM][DSTATE + 1];
    __shared__ float sC2[QC][DSTATE];
    __shared__ float sExp[QC];

    size_t pbase = ((size_t)((b * NCHUNK + c) * NHEADS + h)) * HEADDIM * DSTATE;
    for (int i = tid; i < HEADDIM * DSTATE; i += 256)
        sPrev[i >> 4][i & 15] = g_prev[pbase + i];
    for (int i = tid; i < QC * DSTATE; i += 256) {
        int q = i >> 4, n = i & 15;
        sC2[q][n] = g_xbc[(size_t)(t0 + q) * CONVDIM + DINNER + DSTATE + n];
    }
    if (tid < QC) sExp[tid] = __expf(g_cs[(t0 + tid) * NHEADS + h]);
    __syncthreads();

    for (int i = tid; i < QC * HEADDIM; i += 256) {
        int q = i >> 8, p = i & 255;
        float d = 0.f;
        #pragma unroll
        for (int n = 0; n < DSTATE; n++) d += sC2[q][n] * sPrev[p][n];
        size_t yi = (size_t)(t0 + q) * DINNER + h * HEADDIM + p;
        g_y[yi] += sExp[q] * d;
    }
}

// ---------------- gate (silu(z)) + RMSNorm -> tf32 bits ---------------------
__global__ void __launch_bounds__(256) gate_norm_kernel(const float* __restrict__ norm_w) {
    int t = blockIdx.x, tid = threadIdx.x;
    __shared__ float red[256];
    float v[8];
    float ss = 0.f;
    #pragma unroll
    for (int r = 0; r < 8; r++) {
        int i = r * 256 + tid;
        float y = g_y[(size_t)t * DINNER + i];
        float z = g_zx[(size_t)t * ZXS + i];
        float w = y * (z / (1.f + __expf(-z)));
        v[r] = w;
        ss += w * w;
    }
    red[tid] = ss;
    __syncthreads();
    for (int s = 128; s > 0; s >>= 1) {
        if (tid < s) red[tid] += red[tid + s];
        __syncthreads();
    }
    float scale = rsqrtf(red[0] / (float)DINNER + 1e-5f);
    #pragma unroll
    for (int r = 0; r < 8; r++) {
        int i = r * 256 + tid;
        g_yn[(size_t)t * DINNER + i] = __uint_as_float(f2tf(v[r] * scale * norm_w[i]));
    }
}

// ---------------- launch ----------------------------------------------------
extern "C" void kernel_launch(void* const* d_in, const int* in_sizes, int n_in,
                              void* d_out, int out_size) {
    const float* u       = (const float*)d_in[0];
    const float* W_in    = (const float*)d_in[1];
    const float* conv_w  = (const float*)d_in[2];
    const float* conv_b  = (const float*)d_in[3];
    const float* dt_bias = (const float*)d_in[4];
    const float* A_log   = (const float*)d_in[5];
    const float* Dv      = (const float*)d_in[6];
    const float* norm_w  = (const float*)d_in[7];
    const float* W_out   = (const float*)d_in[8];
    float* out = (float*)d_out;

    void* p;
    cudaGetSymbolAddress(&p, g_zx);     float* zx  = (float*)p;
    cudaGetSymbolAddress(&p, g_Win);    float* win = (float*)p;
    cudaGetSymbolAddress(&p, g_u32);    float* u32 = (float*)p;
    cudaGetSymbolAddress(&p, g_Wout32); float* wo32 = (float*)p;
    cudaGetSymbolAddress(&p, g_yn);     float* yn  = (float*)p;

    cudaFuncSetAttribute(mma_gemm, cudaFuncAttributeMaxDynamicSharedMemorySize, GEMM_SMEM);

    // prepasses: tf32 conversion of GEMM operands
    pad_win_kernel<<<(DMODEL * ZXS + 255) / 256, 256>>>(W_in);
    cvt_tf32_kernel<<<((NTOK * DMODEL / 4) + 255) / 256, 256>>>(u, u32, NTOK * DMODEL / 4);
    cvt_tf32_kernel<<<((DINNER * DMODEL / 4) + 255) / 256, 256>>>(W_out, wo32, DINNER * DMODEL / 4);

    // 1) in-projection
    mma_gemm<<<dim3(ZXS / BN, NTOK / BM), 128, GEMM_SMEM>>>(
        NTOK, ZXS, DMODEL, u32, DMODEL, win, ZXS, zx, ZXS);

    // 2) conv + silu
    conv_silu_kernel<<<dim3((CONVDIM + CT_C - 1) / CT_C, NTOK / CT_T), 256>>>(conv_w, conv_b);

    // 3) per-chunk (dt folded in)
    chunk_kernel<<<dim3(NHEADS, NCHUNK, BATCH), 256>>>(A_log, Dv, dt_bias);

    // 4) inter-chunk scan
    scan_kernel<<<dim3(HEADDIM / 32, NHEADS, BATCH), 512>>>();

    // 5) Y_off
    yoff_kernel<<<dim3(NHEADS, NCHUNK, BATCH), 256>>>();

    // 6) gating + RMSNorm (emits tf32 bits)
    gate_norm_kernel<<<NTOK, 256>>>(norm_w);

    // 7) out-projection
    mma_gemm<<<dim3(DMODEL / BN, NTOK / BM), 128, GEMM_SMEM>>>(
        NTOK, DMODEL, DINNER, yn, DINNER, wo32, DMODEL, out, DMODEL);
}

// round 7
// speedup vs baseline: 3.6160x; 1.1295x over previous
#include <cuda_runtime.h>
#include <math.h>
#include <stdint.h>

#define BATCH   4
#define SEQLEN  4096
#define DMODEL  1024
#define DINNER  2048
#define DSTATE  16
#define NHEADS  8
#define HEADDIM 256
#define CONVDIM 2080
#define DPROJ   4136
#define ZXS     4224
#define QC      64
#define NCHUNK  (SEQLEN/QC)
#define NTOK    (BATCH*SEQLEN)

// ---------------- scratch ----------------------------------------------------
__device__ float g_zx[(size_t)NTOK * ZXS];          // in-proj output (normal layout)
__device__ float g_Win[(size_t)DMODEL * ZXS];       // W_in, B-permuted tf32 bits
__device__ float g_u32[(size_t)NTOK * DMODEL];      // u, A-permuted tf32 bits
__device__ float g_Wout32[(size_t)DINNER * DMODEL]; // W_out, B-permuted tf32 bits
__device__ float g_xbc[(size_t)NTOK * CONVDIM];
__device__ float g_cs[NTOK * NHEADS];
__device__ float g_states[BATCH * NCHUNK * NHEADS * HEADDIM * DSTATE];
__device__ float g_prev[BATCH * NCHUNK * NHEADS * HEADDIM * DSTATE];
__device__ float g_y[(size_t)NTOK * DINNER];
__device__ float g_yn[(size_t)NTOK * DINNER];       // gated+normalized, A-permuted tf32

// ---------------- permuted-layout offset helpers ----------------------------
// A fragment-major: block (m16, k8) -> 128 floats: lane=(m&7)*4+(k&3), reg=(m>>3&1)+2*(k>>2&1)
__device__ __forceinline__ size_t aoff(int m, int k, int K8) {
    return ((size_t)((m >> 4) * K8 + (k >> 3)) << 7)
         + (((m & 7) << 2) + (k & 3) << 2) + ((m >> 3) & 1) + (((k >> 2) & 1) << 1);
}
// B fragment-major: block (n16, k8): lane=(n&7)*4+(k&3), reg=((k>>2)&1)+2*((n>>3)&1)
__device__ __forceinline__ size_t boff(int n, int k, int K8) {
    return ((size_t)((n >> 4) * K8 + (k >> 3)) << 7)
         + (((n & 7) << 2) + (k & 3) << 2) + ((k >> 2) & 1) + (((n >> 3) & 1) << 1);
}

__device__ __forceinline__ unsigned f2tf(float f) {
    unsigned r;
    asm("cvt.rna.tf32.f32 %0, %1;" : "=r"(r) : "f"(f));
    return r;
}
__device__ __forceinline__ void cpa16(float* s, const float* gp) {
    unsigned saddr = (unsigned)__cvta_generic_to_shared(s);
    asm volatile("cp.async.cg.shared.global [%0], [%1], 16;" :: "r"(saddr), "l"(gp));
}
__device__ __forceinline__ void mma_tf32(float c[4], const unsigned a[4],
                                         unsigned b0, unsigned b1) {
    asm volatile(
        "mma.sync.aligned.m16n8k8.row.col.f32.tf32.tf32.f32 "
        "{%0,%1,%2,%3}, {%4,%5,%6,%7}, {%8,%9}, {%0,%1,%2,%3};"
        : "+f"(c[0]), "+f"(c[1]), "+f"(c[2]), "+f"(c[3])
        : "r"(a[0]), "r"(a[1]), "r"(a[2]), "r"(a[3]), "r"(b0), "r"(b1));
}

// ======================= tf32 tensor-core GEMM (permuted operands) ==========
// C[M,N] = A@B^T. A: A-perm [M/16][K/8][128], B: B-perm [N/16][K/8][128].
// 128x128 block, 256 threads, 8 warps (2m x 4n), 64x32 warp tiles.
#define GEMM_SMEM (4 * 4096 * 4)   // 2 stages x (A 4096 + B 4096 floats)

extern __shared__ float g_smem[];

__global__ void __launch_bounds__(256, 2)
mma_gemm(const float* __restrict__ A, const float* __restrict__ B,
         float* __restrict__ C, int K, int ldc) {
    float* sA = g_smem;            // [2][8 mgrp][4 k8][128]
    float* sB = g_smem + 2 * 4096; // [2][8 ngrp][4 k8][128]

    int tid = threadIdx.x, warp = tid >> 5, lane = tid & 31;
    int g = lane >> 2, tg = lane & 3;
    int warp_m = warp >> 2;        // 0..1 (x64 rows)
    int warp_n = warp & 3;         // 0..3 (x32 cols)
    int m0 = blockIdx.y * 128, n0 = blockIdx.x * 128;
    int K8 = K >> 3;
    const float* Abase = A + (size_t)(m0 >> 4) * K8 * 128;
    const float* Bbase = B + (size_t)(n0 >> 4) * K8 * 128;

    float acc[4][4][4];
    #pragma unroll
    for (int mi = 0; mi < 4; mi++)
        #pragma unroll
        for (int ni = 0; ni < 4; ni++)
            #pragma unroll
            for (int r = 0; r < 4; r++) acc[mi][ni][r] = 0.f;

    const int KT = K >> 5;

    auto load_tile = [&](int kt, int s) {
        #pragma unroll
        for (int j = 0; j < 4; j++) {
            int u = tid + 256 * j;           // 16B unit id, 0..1023
            int grp = u >> 7;                // 0..7 (m/n group)
            int within = u & 127;            // 0..127 (16B units inside 512-float slice)
            cpa16(&sA[s * 4096 + u * 4],
                  Abase + (size_t)grp * (K8 * 128) + kt * 512 + within * 4);
            cpa16(&sB[s * 4096 + u * 4],
                  Bbase + (size_t)grp * (K8 * 128) + kt * 512 + within * 4);
        }
        asm volatile("cp.async.commit_group;");
    };

    load_tile(0, 0);

    for (int kt = 0; kt < KT; kt++) {
        int s = kt & 1;
        if (kt + 1 < KT) {
            load_tile(kt + 1, s ^ 1);
            asm volatile("cp.async.wait_group 1;");
        } else {
            asm volatile("cp.async.wait_group 0;");
        }
        __syncthreads();

        const float* wA = sA + s * 4096 + warp_m * 4 * 512;
        const float* wB = sB + s * 4096 + warp_n * 2 * 512;

        #pragma unroll
        for (int ks = 0; ks < 4; ks++) {
            unsigned afr[4][4], bfr[4][2];
            #pragma unroll
            for (int mi = 0; mi < 4; mi++) {
                float4 v = *(const float4*)(wA + mi * 512 + ks * 128 + lane * 4);
                afr[mi][0] = __float_as_uint(v.x);
                afr[mi][1] = __float_as_uint(v.y);
                afr[mi][2] = __float_as_uint(v.z);
                afr[mi][3] = __float_as_uint(v.w);
            }
            #pragma unroll
            for (int nb = 0; nb < 2; nb++) {
                float4 v = *(const float4*)(wB + nb * 512 + ks * 128 + lane * 4);
                bfr[2 * nb][0]     = __float_as_uint(v.x);
                bfr[2 * nb][1]     = __float_as_uint(v.y);
                bfr[2 * nb + 1][0] = __float_as_uint(v.z);
                bfr[2 * nb + 1][1] = __float_as_uint(v.w);
            }
            #pragma unroll
            for (int mi = 0; mi < 4; mi++)
                #pragma unroll
                for (int ni = 0; ni < 4; ni++)
                    mma_tf32(acc[mi][ni], afr[mi], bfr[ni][0], bfr[ni][1]);
        }
        __syncthreads();
    }

    #pragma unroll
    for (int mi = 0; mi < 4; mi++) {
        #pragma unroll
        for (int ni = 0; ni < 4; ni++) {
            int row = m0 + warp_m * 64 + mi * 16 + g;
            int col = n0 + warp_n * 32 + ni * 8 + tg * 2;
            float2 v0 = make_float2(acc[mi][ni][0], acc[mi][ni][1]);
            float2 v1 = make_float2(acc[mi][ni][2], acc[mi][ni][3]);
            *(float2*)&C[(size_t)row * ldc + col] = v0;
            *(float2*)&C[(size_t)(row + 8) * ldc + col] = v1;
        }
    }
}

// ---------------- prepasses --------------------------------------------------
__global__ void cvt_u_kernel(const float* __restrict__ u) {
    int i = blockIdx.x * 256 + threadIdx.x;
    if (i >= NTOK * DMODEL) return;
    int m = i >> 10, k = i & 1023;
    g_u32[aoff(m, k, 128)] = __uint_as_float(f2tf(u[i]));
}
__global__ void pad_win_kernel(const float* __restrict__ W_in) {
    int i = blockIdx.x * 256 + threadIdx.x;
    if (i >= DMODEL * ZXS) return;
    int k = i / ZXS, n = i - k * ZXS;
    float v = (n < DPROJ) ? __uint_as_float(f2tf(W_in[(size_t)k * DPROJ + n])) : 0.f;
    g_Win[boff(n, k, 128)] = v;
}
__global__ void cvt_wout_kernel(const float* __restrict__ W_out) {
    int i = blockIdx.x * 256 + threadIdx.x;
    if (i >= DINNER * DMODEL) return;
    int k = i >> 10, n = i & 1023;
    g_Wout32[boff(n, k, 256)] = __uint_as_float(f2tf(W_out[i]));
}

// ---------------- tiled depthwise causal conv + silu ------------------------
#define CT_T 64
#define CT_C 128
__global__ void __launch_bounds__(256)
conv_silu_kernel(const float* __restrict__ conv_w, const float* __restrict__ conv_b) {
    __shared__ float sx[CT_T + 3][CT_C];
    int c0 = blockIdx.x * CT_C;
    int t0 = blockIdx.y * CT_T;
    int tid = threadIdx.x;
    bool bstart = ((t0 & (SEQLEN - 1)) == 0);

    for (int i = tid; i < (CT_T + 3) * CT_C; i += 256) {
        int r = i / CT_C, cl = i - r * CT_C;
        int c = c0 + cl;
        float v = 0.f;
        if (c < CONVDIM && !(bstart && r < 3))
            v = g_zx[(size_t)(t0 - 3 + r) * ZXS + DINNER + c];
        sx[r][cl] = v;
    }
    __syncthreads();

    int cl = tid & (CT_C - 1);
    int tbase = (tid >> 7) * (CT_T / 2);
    int c = c0 + cl;
    if (c >= CONVDIM) return;
    float w0 = conv_w[c * 4 + 0], w1 = conv_w[c * 4 + 1];
    float w2 = conv_w[c * 4 + 2], w3 = conv_w[c * 4 + 3];
    float bb = conv_b[c];
    #pragma unroll 8
    for (int i = 0; i < CT_T / 2; i++) {
        int tl = tbase + i;
        float a = bb + sx[tl][cl] * w0 + sx[tl + 1][cl] * w1
                     + sx[tl + 2][cl] * w2 + sx[tl + 3][cl] * w3;
        g_xbc[(size_t)(t0 + tl) * CONVDIM + c] = a / (1.f + __expf(-a));
    }
}

// ---------------- per-chunk: dt, cumsum, M, Y_diag(+D*x), states ------------
__global__ void __launch_bounds__(256)
chunk_kernel(const float* __restrict__ A_log, const float* __restrict__ Dp,
             const float* __restrict__ dt_bias) {
    int h = blockIdx.x, c = blockIdx.y, b = blockIdx.z;
    int t0 = b * SEQLEN + c * QC;
    int tid = threadIdx.x;

    __shared__ float sB[QC][DSTATE];
    __shared__ float sC[QC][DSTATE];
    __shared__ float sdt[QC], scs[QC];
    __shared__ float sMt[QC][QC];
    __shared__ float sE[QC][DSTATE];
    __shared__ float sx[QC][QC];

    for (int i = tid; i < QC * DSTATE; i += 256) {
        int q = i >> 4, n = i & 15;
        size_t base = (size_t)(t0 + q) * CONVDIM + DINNER;
        sB[q][n] = g_xbc[base + n];
        sC[q][n] = g_xbc[base + DSTATE + n];
    }
    if (tid < QC) {
        float v = g_zx[(size_t)(t0 + tid) * ZXS + DINNER + CONVDIM + h] + dt_bias[h];
        sdt[tid] = (v > 20.f) ? v : log1pf(expf(v));
    }
    __syncthreads();

    float A = -expf(A_log[h]);
    if (tid == 0) {
        float run = 0.f;
        for (int q = 0; q < QC; q++) { run += sdt[q] * A; scs[q] = run; }
    }
    __syncthreads();
    if (tid < QC) g_cs[(t0 + tid) * NHEADS + h] = scs[tid];

    float cl = scs[QC - 1];
    for (int i = tid; i < QC * DSTATE; i += 256) {
        int q = i >> 4, n = i & 15;
        sE[q][n] = sB[q][n] * __expf(cl - scs[q]) * sdt[q];
    }
    for (int i = tid; i < QC * QC; i += 256) {
        int q = i >> 6, s = i & 63;
        float v = 0.f;
        if (s <= q) {
            float d = 0.f;
            #pragma unroll
            for (int n = 0; n < DSTATE; n++) d += sC[q][n] * sB[s][n];
            v = __expf(scs[q] - scs[s]) * d * sdt[s];
        }
        sMt[s][q] = v;
    }
    __syncthreads();

    float Dh = Dp[h];
    int q0 = (tid >> 4) * 4;
    int p0 = (tid & 15) * 4;
    int pS = tid >> 2;
    int n0 = (tid & 3) * 4;

    for (int pt = 0; pt < 4; pt++) {
        int pbase = pt * QC;
        for (int i = tid; i < QC * QC; i += 256) {
            int q = i >> 6, pl = i & 63;
            sx[q][pl] = g_xbc[(size_t)(t0 + q) * CONVDIM + h * HEADDIM + pbase + pl];
        }
        __syncthreads();

        float acc[4][4];
        #pragma unroll
        for (int i = 0; i < 4; i++)
            #pragma unroll
            for (int j = 0; j < 4; j++) acc[i][j] = 0.f;

        for (int s = 0; s < QC; s++) {
            float4 m4 = *(const float4*)&sMt[s][q0];
            float4 x4 = *(const float4*)&sx[s][p0];
            float mv[4] = {m4.x, m4.y, m4.z, m4.w};
            float xv[4] = {x4.x, x4.y, x4.z, x4.w};
            #pragma unroll
            for (int i = 0; i < 4; i++)
                #pragma unroll
                for (int j = 0; j < 4; j++)
                    acc[i][j] += mv[i] * xv[j];
        }
        #pragma unroll
        for (int i = 0; i < 4; i++) {
            int q = q0 + i;
            float4 o;
            o.x = acc[i][0] + Dh * sx[q][p0 + 0];
            o.y = acc[i][1] + Dh * sx[q][p0 + 1];
            o.z = acc[i][2] + Dh * sx[q][p0 + 2];
            o.w = acc[i][3] + Dh * sx[q][p0 + 3];
            *(float4*)&g_y[(size_t)(t0 + q) * DINNER + h * HEADDIM + pbase + p0] = o;
        }

        float accS[4] = {0.f, 0.f, 0.f, 0.f};
        for (int q = 0; q < QC; q++) {
            float xs = sx[q][pS];
            float4 e4 = *(const float4*)&sE[q][n0];
            accS[0] += e4.x * xs;
            accS[1] += e4.y * xs;
            accS[2] += e4.z * xs;
            accS[3] += e4.w * xs;
        }
        size_t sb = ((size_t)((b * NCHUNK + c) * NHEADS + h)) * HEADDIM * DSTATE
                    + (size_t)(pbase + pS) * DSTATE + n0;
        *(float4*)&g_states[sb] = make_float4(accS[0], accS[1], accS[2], accS[3]);
        __syncthreads();
    }
}

// ---------------- inter-chunk scan ------------------------------------------
__global__ void __launch_bounds__(512) scan_kernel() {
    int pb = blockIdx.x, h = blockIdx.y, b = blockIdx.z;
    int tid = threadIdx.x;
    int pl = tid >> 4, n = tid & 15;
    int p = pb * 32 + pl;
    float carry = 0.f;
    for (int c = 0; c < NCHUNK; c++) {
        size_t idx = ((size_t)((b * NCHUNK + c) * NHEADS + h)) * HEADDIM * DSTATE
                     + (size_t)p * DSTATE + n;
        g_prev[idx] = carry;
        float dec = __expf(g_cs[(b * SEQLEN + c * QC + QC - 1) * NHEADS + h]);
        carry = dec * carry + g_states[idx];
    }
}

// ---------------- Y_off ------------------------------------------------------
__global__ void __launch_bounds__(256) yoff_kernel() {
    int h = blockIdx.x, c = blockIdx.y, b = blockIdx.z;
    int t0 = b * SEQLEN + c * QC;
    int tid = threadIdx.x;

    __shared__ float sPrev[HEADDIM][DSTATE + 1];
    __shared__ float sC2[QC][DSTATE];
    __shared__ float sExp[QC];

    size_t pbase = ((size_t)((b * NCHUNK + c) * NHEADS + h)) * HEADDIM * DSTATE;
    for (int i = tid; i < HEADDIM * DSTATE; i += 256)
        sPrev[i >> 4][i & 15] = g_prev[pbase + i];
    for (int i = tid; i < QC * DSTATE; i += 256) {
        int q = i >> 4, n = i & 15;
        sC2[q][n] = g_xbc[(size_t)(t0 + q) * CONVDIM + DINNER + DSTATE + n];
    }
    if (tid < QC) sExp[tid] = __expf(g_cs[(t0 + tid) * NHEADS + h]);
    __syncthreads();

    for (int i = tid; i < QC * HEADDIM; i += 256) {
        int q = i >> 8, p = i & 255;
        float d = 0.f;
        #pragma unroll
        for (int n = 0; n < DSTATE; n++) d += sC2[q][n] * sPrev[p][n];
        size_t yi = (size_t)(t0 + q) * DINNER + h * HEADDIM + p;
        g_y[yi] += sExp[q] * d;
    }
}

// ---------------- gate + RMSNorm -> A-permuted tf32 bits --------------------
__global__ void __launch_bounds__(256) gate_norm_kernel(const float* __restrict__ norm_w) {
    int t = blockIdx.x, tid = threadIdx.x;
    __shared__ float red[256];
    float v[8];
    float ss = 0.f;
    #pragma unroll
    for (int r = 0; r < 8; r++) {
        int i = r * 256 + tid;
        float y = g_y[(size_t)t * DINNER + i];
        float z = g_zx[(size_t)t * ZXS + i];
        float w = y * (z / (1.f + __expf(-z)));
        v[r] = w;
        ss += w * w;
    }
    red[tid] = ss;
    __syncthreads();
    for (int s = 128; s > 0; s >>= 1) {
        if (tid < s) red[tid] += red[tid + s];
        __syncthreads();
    }
    float scale = rsqrtf(red[0] / (float)DINNER + 1e-5f);
    #pragma unroll
    for (int r = 0; r < 8; r++) {
        int i = r * 256 + tid;
        g_yn[aoff(t, i, 256)] = __uint_as_float(f2tf(v[r] * scale * norm_w[i]));
    }
}

// ---------------- launch ----------------------------------------------------
extern "C" void kernel_launch(void* const* d_in, const int* in_sizes, int n_in,
                              void* d_out, int out_size) {
    const float* u       = (const float*)d_in[0];
    const float* W_in    = (const float*)d_in[1];
    const float* conv_w  = (const float*)d_in[2];
    const float* conv_b  = (const float*)d_in[3];
    const float* dt_bias = (const float*)d_in[4];
    const float* A_log   = (const float*)d_in[5];
    const float* Dv      = (const float*)d_in[6];
    const float* norm_w  = (const float*)d_in[7];
    const float* W_out   = (const float*)d_in[8];
    float* out = (float*)d_out;

    void* p;
    cudaGetSymbolAddress(&p, g_zx);     float* zx   = (float*)p;
    cudaGetSymbolAddress(&p, g_Win);    float* win  = (float*)p;
    cudaGetSymbolAddress(&p, g_u32);    float* u32  = (float*)p;
    cudaGetSymbolAddress(&p, g_Wout32); float* wo32 = (float*)p;
    cudaGetSymbolAddress(&p, g_yn);     float* yn   = (float*)p;

    cudaFuncSetAttribute(mma_gemm, cudaFuncAttributeMaxDynamicSharedMemorySize, GEMM_SMEM);

    // prepasses: permuted tf32 operands
    pad_win_kernel<<<(DMODEL * ZXS + 255) / 256, 256>>>(W_in);
    cvt_u_kernel<<<(NTOK * DMODEL + 255) / 256, 256>>>(u);
    cvt_wout_kernel<<<(DINNER * DMODEL + 255) / 256, 256>>>(W_out);

    // 1) in-projection: [16384 x 1024] @ [1024 x 4224] -> zx
    mma_gemm<<<dim3(ZXS / 128, NTOK / 128), 256, GEMM_SMEM>>>(u32, win, zx, DMODEL, ZXS);

    // 2) conv + silu
    conv_silu_kernel<<<dim3((CONVDIM + CT_C - 1) / CT_C, NTOK / CT_T), 256>>>(conv_w, conv_b);

    // 3) per-chunk
    chunk_kernel<<<dim3(NHEADS, NCHUNK, BATCH), 256>>>(A_log, Dv, dt_bias);

    // 4) inter-chunk scan
    scan_kernel<<<dim3(HEADDIM / 32, NHEADS, BATCH), 512>>>();

    // 5) Y_off
    yoff_kernel<<<dim3(NHEADS, NCHUNK, BATCH), 256>>>();

    // 6) gating + RMSNorm (emits permuted tf32)
    gate_norm_kernel<<<NTOK, 256>>>(norm_w);

    // 7) out-projection: [16384 x 2048] @ [2048 x 1024] -> out
    mma_gemm<<<dim3(DMODEL / 128, NTOK / 128), 256, GEMM_SMEM>>>(yn, wo32, out, DINNER, DMODEL);
}